// round 2
// baseline (speedup 1.0000x reference)
#include <cuda_runtime.h>
#include <stdint.h>

// Fixed problem shape: N=100000 nodes, E=1600000 edges, dims 128 -> 128 -> 40.
#define NMAX 100352
#define EMAX 1600000

// ---------------- device scratch (no allocations allowed) ----------------
__device__ int   g_deg[NMAX];
__device__ int   g_rowptr[NMAX + 1];
__device__ int   g_cursor[NMAX];
__device__ int   g_blocksums[256];
__device__ int   g_csrsrc[EMAX];
__device__ float g_dinv[NMAX];
__device__ float g_p[(size_t)NMAX * 128];              // scaled features
__device__ float g_hidden_scratch[(size_t)NMAX * 128]; // fallback hidden storage
__device__ int   g_idx64;                              // 1 if edge_index is int64

// ---------------- dtype detection ----------------
// int64 indices < 2^31 have zero high words -> odd int32 lanes all zero.
__global__ void k_detect(const int* __restrict__ ei32) {
    int any = 0;
#pragma unroll
    for (int k = 0; k < 64; ++k) any |= ei32[2 * k + 1];
    g_idx64 = (any == 0) ? 1 : 0;
}

__device__ __forceinline__ int edge_at(const void* ei, long long i) {
    if (g_idx64) return (int)((const long long*)ei)[i];
    return ((const int*)ei)[i];
}

// ---------------- degree / CSR build ----------------
__global__ void k_deg_zero(int n) {
    int i = blockIdx.x * blockDim.x + threadIdx.x;
    if (i < n) g_deg[i] = 0;
}

__global__ void k_deg_count(const void* __restrict__ ei, int E, int n) {
    int e = blockIdx.x * blockDim.x + threadIdx.x;
    if (e < E) {
        int d = edge_at(ei, (long long)E + e);
        if ((unsigned)d < (unsigned)n) atomicAdd(&g_deg[d], 1);
    }
}

// block-level exclusive scan of g_deg -> g_rowptr, block totals -> g_blocksums
__global__ void k_scan_block(int n) {
    __shared__ int ssum[256];
    int tid = threadIdx.x;
    int base = blockIdx.x * 1024 + tid * 4;
    int v0 = (base + 0 < n) ? g_deg[base + 0] : 0;
    int v1 = (base + 1 < n) ? g_deg[base + 1] : 0;
    int v2 = (base + 2 < n) ? g_deg[base + 2] : 0;
    int v3 = (base + 3 < n) ? g_deg[base + 3] : 0;
    int p0 = 0, p1 = v0, p2 = v0 + v1, p3 = v0 + v1 + v2;
    int total = p3 + v3;
    ssum[tid] = total;
    __syncthreads();
    for (int off = 1; off < 256; off <<= 1) {
        int v = 0;
        if (tid >= off) v = ssum[tid - off];
        __syncthreads();
        if (tid >= off) ssum[tid] += v;
        __syncthreads();
    }
    int excl = ssum[tid] - total;
    if (base + 0 < n) g_rowptr[base + 0] = excl + p0;
    if (base + 1 < n) g_rowptr[base + 1] = excl + p1;
    if (base + 2 < n) g_rowptr[base + 2] = excl + p2;
    if (base + 3 < n) g_rowptr[base + 3] = excl + p3;
    if (tid == 255) g_blocksums[blockIdx.x] = ssum[255];
}

__global__ void k_scan_top(int nb) {
    __shared__ int s[128];
    int tid = threadIdx.x;
    int orig = (tid < nb) ? g_blocksums[tid] : 0;
    s[tid] = orig;
    __syncthreads();
    for (int off = 1; off < 128; off <<= 1) {
        int v = 0;
        if (tid >= off) v = s[tid - off];
        __syncthreads();
        if (tid >= off) s[tid] += v;
        __syncthreads();
    }
    if (tid < nb) g_blocksums[tid] = s[tid] - orig;
}

__global__ void k_scan_finish(int n, int E) {
    int i = blockIdx.x * blockDim.x + threadIdx.x;
    if (i < n) {
        int v = g_rowptr[i] + g_blocksums[i >> 10];
        g_rowptr[i] = v;
        g_cursor[i] = v;
        g_dinv[i]   = rsqrtf((float)(g_deg[i] + 1));
    }
    if (i == 0) g_rowptr[n] = E;
}

__global__ void k_scatter(const void* __restrict__ ei, int E, int n) {
    int e = blockIdx.x * blockDim.x + threadIdx.x;
    if (e < E) {
        int s = edge_at(ei, e);
        int d = edge_at(ei, (long long)E + e);
        if ((unsigned)d < (unsigned)n && (unsigned)s < (unsigned)n) {
            int pos = atomicAdd(&g_cursor[d], 1);
            if (pos < EMAX) g_csrsrc[pos] = s;
        }
    }
}

// ---------------- GEMM: P[node, f0:f0+FT] = dinv[node] * (X[node,:] @ W[:, f0:f0+FT]) ----
template <int FT>
__launch_bounds__(256)
__global__ void k_gemm(const float* __restrict__ X, const float* __restrict__ W,
                       int ldw, int ldp, int n) {
    __shared__ float sW[32 * FT];
    __shared__ float sx[256 * 33];
    const int tid = threadIdx.x;
    const int n0 = blockIdx.x * 256;
    const int f0 = blockIdx.y * FT;
    float acc[FT];
#pragma unroll
    for (int j = 0; j < FT; ++j) acc[j] = 0.f;

    for (int kc = 0; kc < 4; ++kc) {
        __syncthreads();
        for (int t = tid; t < 256 * 8; t += 256) {
            int r = t >> 3, c4 = (t & 7) * 4;
            int node = n0 + r;
            float4 xv = make_float4(0.f, 0.f, 0.f, 0.f);
            if (node < n)
                xv = *(const float4*)(X + (size_t)node * 128 + kc * 32 + c4);
            float* d = &sx[r * 33 + c4];
            d[0] = xv.x; d[1] = xv.y; d[2] = xv.z; d[3] = xv.w;
        }
        for (int t = tid; t < 32 * (FT / 4); t += 256) {
            int k = t / (FT / 4), q = t % (FT / 4);
            float4 wv = *(const float4*)(W + (size_t)(kc * 32 + k) * ldw + f0 + q * 4);
            *(float4*)(&sW[k * FT + q * 4]) = wv;
        }
        __syncthreads();
#pragma unroll
        for (int kk = 0; kk < 32; ++kk) {
            float xv = sx[tid * 33 + kk];
            const float4* wrow = (const float4*)(&sW[kk * FT]);
#pragma unroll
            for (int j4 = 0; j4 < FT / 4; ++j4) {
                float4 w = wrow[j4];
                acc[j4 * 4 + 0] = fmaf(xv, w.x, acc[j4 * 4 + 0]);
                acc[j4 * 4 + 1] = fmaf(xv, w.y, acc[j4 * 4 + 1]);
                acc[j4 * 4 + 2] = fmaf(xv, w.z, acc[j4 * 4 + 2]);
                acc[j4 * 4 + 3] = fmaf(xv, w.w, acc[j4 * 4 + 3]);
            }
        }
    }
    int node = n0 + tid;
    if (node < n) {
        float di = g_dinv[node];
        float* P = g_p + (size_t)node * ldp + f0;
#pragma unroll
        for (int j4 = 0; j4 < FT / 4; ++j4) {
            float4 o;
            o.x = acc[j4 * 4 + 0] * di;
            o.y = acc[j4 * 4 + 1] * di;
            o.z = acc[j4 * 4 + 2] * di;
            o.w = acc[j4 * 4 + 3] * di;
            *(float4*)(P + j4 * 4) = o;
        }
    }
}

// ---------------- aggregation: one warp per node, gather-only -------------
__global__ void k_agg128(const float* __restrict__ bias, float* __restrict__ out, int n) {
    int warp = (blockIdx.x * blockDim.x + threadIdx.x) >> 5;
    if (warp >= n) return;
    int lane = threadIdx.x & 31;
    const float4* p4 = (const float4*)g_p;
    float4 acc = p4[(size_t)warp * 32 + lane];           // self loop
    int j = g_rowptr[warp];
    int end = g_rowptr[warp + 1];
    for (; j + 4 <= end; j += 4) {
        int s0 = g_csrsrc[j], s1 = g_csrsrc[j + 1], s2 = g_csrsrc[j + 2], s3 = g_csrsrc[j + 3];
        float4 v0 = __ldg(&p4[(size_t)s0 * 32 + lane]);
        float4 v1 = __ldg(&p4[(size_t)s1 * 32 + lane]);
        float4 v2 = __ldg(&p4[(size_t)s2 * 32 + lane]);
        float4 v3 = __ldg(&p4[(size_t)s3 * 32 + lane]);
        acc.x += v0.x + v1.x + v2.x + v3.x;
        acc.y += v0.y + v1.y + v2.y + v3.y;
        acc.z += v0.z + v1.z + v2.z + v3.z;
        acc.w += v0.w + v1.w + v2.w + v3.w;
    }
    for (; j < end; ++j) {
        int s = g_csrsrc[j];
        float4 v = __ldg(&p4[(size_t)s * 32 + lane]);
        acc.x += v.x; acc.y += v.y; acc.z += v.z; acc.w += v.w;
    }
    float di = g_dinv[warp];
    float4 bb = ((const float4*)bias)[lane];
    float4 o;
    o.x = fmaxf(fmaf(acc.x, di, bb.x), 0.f);
    o.y = fmaxf(fmaf(acc.y, di, bb.y), 0.f);
    o.z = fmaxf(fmaf(acc.z, di, bb.z), 0.f);
    o.w = fmaxf(fmaf(acc.w, di, bb.w), 0.f);
    ((float4*)out)[(size_t)warp * 32 + lane] = o;
}

__global__ void k_agg40(const float* __restrict__ bias, float* __restrict__ out, int n) {
    int warp = (blockIdx.x * blockDim.x + threadIdx.x) >> 5;
    if (warp >= n) return;
    int lane = threadIdx.x & 31;
    bool act = lane < 20;
    const float2* p2 = (const float2*)g_p;
    float2 acc = make_float2(0.f, 0.f);
    if (act) acc = p2[(size_t)warp * 20 + lane];          // self loop
    int j = g_rowptr[warp];
    int end = g_rowptr[warp + 1];
    for (; j + 4 <= end; j += 4) {
        int s0 = g_csrsrc[j], s1 = g_csrsrc[j + 1], s2 = g_csrsrc[j + 2], s3 = g_csrsrc[j + 3];
        if (act) {
            float2 v0 = __ldg(&p2[(size_t)s0 * 20 + lane]);
            float2 v1 = __ldg(&p2[(size_t)s1 * 20 + lane]);
            float2 v2 = __ldg(&p2[(size_t)s2 * 20 + lane]);
            float2 v3 = __ldg(&p2[(size_t)s3 * 20 + lane]);
            acc.x += v0.x + v1.x + v2.x + v3.x;
            acc.y += v0.y + v1.y + v2.y + v3.y;
        }
    }
    for (; j < end; ++j) {
        int s = g_csrsrc[j];
        if (act) {
            float2 v = __ldg(&p2[(size_t)s * 20 + lane]);
            acc.x += v.x; acc.y += v.y;
        }
    }
    if (act) {
        float di = g_dinv[warp];
        float2 bb = ((const float2*)bias)[lane];
        float2 o;
        o.x = fmaf(acc.x, di, bb.x);
        o.y = fmaf(acc.y, di, bb.y);
        ((float2*)out)[(size_t)warp * 20 + lane] = o;
    }
}

// ---------------- launch ----------------
extern "C" void kernel_launch(void* const* d_in, const int* in_sizes, int n_in,
                              void* d_out, int out_size) {
    const float* x  = (const float*)d_in[0];
    const void*  ei = d_in[1];
    const float* W1 = (const float*)d_in[2];
    const float* b1 = (const float*)d_in[3];
    const float* W2 = (const float*)d_in[4];
    const float* b2 = (const float*)d_in[5];

    int n = in_sizes[0] / 128;
    int E = in_sizes[1] / 2;

    float* out    = (float*)d_out;
    float* logits = out;                       // [n, 40]
    float* hidden;
    if ((size_t)out_size >= (size_t)n * (40 + 128)) {
        hidden = out + (size_t)n * 40;         // [n, 128]
    } else {
        cudaGetSymbolAddress((void**)&hidden, g_hidden_scratch);
    }

    int nb_n = (n + 255) / 256;
    int nb_e = (E + 255) / 256;
    int nb_scan = (n + 1023) / 1024;
    int nb_warp = (n + 7) / 8;

    // edge dtype detection + CSR build
    k_detect     <<<1, 1>>>((const int*)ei);
    k_deg_zero   <<<nb_n, 256>>>(n);
    k_deg_count  <<<nb_e, 256>>>(ei, E, n);
    k_scan_block <<<nb_scan, 256>>>(n);
    k_scan_top   <<<1, 128>>>(nb_scan);
    k_scan_finish<<<nb_n, 256>>>(n, E);
    k_scatter    <<<nb_e, 256>>>(ei, E, n);

    // layer 1
    k_gemm<64><<<dim3(nb_n, 2), 256>>>(x, W1, 128, 128, n);
    k_agg128  <<<nb_warp, 256>>>(b1, hidden, n);

    // layer 2
    k_gemm<40><<<dim3(nb_n, 1), 256>>>(hidden, W2, 40, 40, n);
    k_agg40   <<<nb_warp, 256>>>(b2, logits, n);
}

// round 3
// speedup vs baseline: 1.0001x; 1.0001x over previous
#include <cuda_runtime.h>
#include <stdint.h>

// Fixed problem shape: N=100000 nodes, E=1600000 edges, dims 128 -> 128 -> 40.
#define NMAX 100352
#define EMAX 1600000

// ---------------- device scratch (no allocations allowed) ----------------
__device__ int   g_deg[NMAX];
__device__ int   g_rowptr[NMAX + 1];
__device__ int   g_cursor[NMAX];
__device__ int   g_blocksums[256];
__device__ int   g_csrsrc[EMAX];
__device__ float g_dinv[NMAX];
__device__ float g_p[(size_t)NMAX * 128];              // scaled features
__device__ float g_hidden_scratch[(size_t)NMAX * 128]; // fallback hidden storage
__device__ int   g_idx64;                              // 1 if edge_index is int64

// ---------------- packed f32x2 helpers ----------------
__device__ __forceinline__ unsigned long long pack2(float lo, float hi) {
    unsigned long long r;
    asm("mov.b64 %0, {%1, %2};" : "=l"(r) : "f"(lo), "f"(hi));
    return r;
}
__device__ __forceinline__ void unpack2(unsigned long long v, float& lo, float& hi) {
    asm("mov.b64 {%0, %1}, %2;" : "=f"(lo), "=f"(hi) : "l"(v));
}
__device__ __forceinline__ unsigned long long fma2(unsigned long long a,
                                                   unsigned long long b,
                                                   unsigned long long c) {
    unsigned long long d;
    asm("fma.rn.f32x2 %0, %1, %2, %3;" : "=l"(d) : "l"(a), "l"(b), "l"(c));
    return d;
}

// ---------------- dtype detection ----------------
__global__ void k_detect(const int* __restrict__ ei32) {
    int any = 0;
#pragma unroll
    for (int k = 0; k < 64; ++k) any |= ei32[2 * k + 1];
    g_idx64 = (any == 0) ? 1 : 0;
}

__device__ __forceinline__ int edge_at(const void* ei, long long i) {
    if (g_idx64) return (int)((const long long*)ei)[i];
    return ((const int*)ei)[i];
}

// ---------------- degree / CSR build ----------------
__global__ void k_deg_count(const void* __restrict__ ei, int E, int n) {
    int e = blockIdx.x * blockDim.x + threadIdx.x;
    if (e < E) {
        int d = edge_at(ei, (long long)E + e);
        if ((unsigned)d < (unsigned)n) atomicAdd(&g_deg[d], 1);
    }
}

__global__ void k_scan_block(int n) {
    __shared__ int ssum[256];
    int tid = threadIdx.x;
    int base = blockIdx.x * 1024 + tid * 4;
    int v0 = (base + 0 < n) ? g_deg[base + 0] : 0;
    int v1 = (base + 1 < n) ? g_deg[base + 1] : 0;
    int v2 = (base + 2 < n) ? g_deg[base + 2] : 0;
    int v3 = (base + 3 < n) ? g_deg[base + 3] : 0;
    int p0 = 0, p1 = v0, p2 = v0 + v1, p3 = v0 + v1 + v2;
    int total = p3 + v3;
    ssum[tid] = total;
    __syncthreads();
    for (int off = 1; off < 256; off <<= 1) {
        int v = 0;
        if (tid >= off) v = ssum[tid - off];
        __syncthreads();
        if (tid >= off) ssum[tid] += v;
        __syncthreads();
    }
    int excl = ssum[tid] - total;
    if (base + 0 < n) g_rowptr[base + 0] = excl + p0;
    if (base + 1 < n) g_rowptr[base + 1] = excl + p1;
    if (base + 2 < n) g_rowptr[base + 2] = excl + p2;
    if (base + 3 < n) g_rowptr[base + 3] = excl + p3;
    if (tid == 255) g_blocksums[blockIdx.x] = ssum[255];
}

__global__ void k_scan_top(int nb) {
    __shared__ int s[128];
    int tid = threadIdx.x;
    int orig = (tid < nb) ? g_blocksums[tid] : 0;
    s[tid] = orig;
    __syncthreads();
    for (int off = 1; off < 128; off <<= 1) {
        int v = 0;
        if (tid >= off) v = s[tid - off];
        __syncthreads();
        if (tid >= off) s[tid] += v;
        __syncthreads();
    }
    if (tid < nb) g_blocksums[tid] = s[tid] - orig;
}

__global__ void k_scan_finish(int n, int E) {
    int i = blockIdx.x * blockDim.x + threadIdx.x;
    if (i < n) {
        int v = g_rowptr[i] + g_blocksums[i >> 10];
        g_rowptr[i] = v;
        g_cursor[i] = v;
        g_dinv[i]   = rsqrtf((float)(g_deg[i] + 1));
    }
    if (i == 0) g_rowptr[n] = E;
}

__global__ void k_scatter(const void* __restrict__ ei, int E, int n) {
    int e = blockIdx.x * blockDim.x + threadIdx.x;
    if (e < E) {
        int s = edge_at(ei, e);
        int d = edge_at(ei, (long long)E + e);
        if ((unsigned)d < (unsigned)n && (unsigned)s < (unsigned)n) {
            int pos = atomicAdd(&g_cursor[d], 1);
            if (pos < EMAX) g_csrsrc[pos] = s;
        }
    }
}

// ---------------- GEMM (f32x2 packed): P = dinv * (X @ W[:, f0:f0+FT]) ----
template <int FT>
__launch_bounds__(256)
__global__ void k_gemm(const float* __restrict__ X, const float* __restrict__ W,
                       int ldw, int ldp, int n) {
    __shared__ __align__(16) float sW[32 * FT];
    __shared__ __align__(16) float sx[256 * 33];
    const int tid = threadIdx.x;
    const int n0 = blockIdx.x * 256;
    const int f0 = blockIdx.y * FT;
    unsigned long long acc2[FT / 2];
#pragma unroll
    for (int j = 0; j < FT / 2; ++j) acc2[j] = 0ULL;

    for (int kc = 0; kc < 4; ++kc) {
        __syncthreads();
        // X chunk: 256 nodes x 32 k
        for (int t = tid; t < 256 * 8; t += 256) {
            int r = t >> 3, c4 = (t & 7) * 4;
            int node = n0 + r;
            float4 xv = make_float4(0.f, 0.f, 0.f, 0.f);
            if (node < n)
                xv = *(const float4*)(X + (size_t)node * 128 + kc * 32 + c4);
            float* d = &sx[r * 33 + c4];
            d[0] = xv.x; d[1] = xv.y; d[2] = xv.z; d[3] = xv.w;
        }
        // W chunk: 32 x FT
        for (int t = tid; t < 32 * (FT / 4); t += 256) {
            int k = t / (FT / 4), q = t % (FT / 4);
            float4 wv = *(const float4*)(W + (size_t)(kc * 32 + k) * ldw + f0 + q * 4);
            *(float4*)(&sW[k * FT + q * 4]) = wv;
        }
        __syncthreads();
#pragma unroll
        for (int kk = 0; kk < 32; ++kk) {
            float xv = sx[tid * 33 + kk];
            unsigned long long xx = pack2(xv, xv);
            const ulonglong2* wrow = (const ulonglong2*)(&sW[kk * FT]);
#pragma unroll
            for (int j4 = 0; j4 < FT / 4; ++j4) {
                ulonglong2 w = wrow[j4];
                acc2[j4 * 2 + 0] = fma2(xx, w.x, acc2[j4 * 2 + 0]);
                acc2[j4 * 2 + 1] = fma2(xx, w.y, acc2[j4 * 2 + 1]);
            }
        }
    }
    int node = n0 + tid;
    if (node < n) {
        float di = g_dinv[node];
        float* P = g_p + (size_t)node * ldp + f0;
#pragma unroll
        for (int j4 = 0; j4 < FT / 4; ++j4) {
            float4 o;
            unpack2(acc2[j4 * 2 + 0], o.x, o.y);
            unpack2(acc2[j4 * 2 + 1], o.z, o.w);
            o.x *= di; o.y *= di; o.z *= di; o.w *= di;
            *(float4*)(P + j4 * 4) = o;
        }
    }
}

// ---------------- aggregation: one warp per node, gather-only -------------
__global__ void k_agg128(const float* __restrict__ bias, float* __restrict__ out, int n) {
    int warp = (blockIdx.x * blockDim.x + threadIdx.x) >> 5;
    if (warp >= n) return;
    int lane = threadIdx.x & 31;
    const float4* p4 = (const float4*)g_p;
    float4 acc = p4[(size_t)warp * 32 + lane];           // self loop
    int j = g_rowptr[warp];
    int end = g_rowptr[warp + 1];
    for (; j + 4 <= end; j += 4) {
        int s0 = g_csrsrc[j], s1 = g_csrsrc[j + 1], s2 = g_csrsrc[j + 2], s3 = g_csrsrc[j + 3];
        float4 v0 = __ldg(&p4[(size_t)s0 * 32 + lane]);
        float4 v1 = __ldg(&p4[(size_t)s1 * 32 + lane]);
        float4 v2 = __ldg(&p4[(size_t)s2 * 32 + lane]);
        float4 v3 = __ldg(&p4[(size_t)s3 * 32 + lane]);
        acc.x += v0.x + v1.x + v2.x + v3.x;
        acc.y += v0.y + v1.y + v2.y + v3.y;
        acc.z += v0.z + v1.z + v2.z + v3.z;
        acc.w += v0.w + v1.w + v2.w + v3.w;
    }
    for (; j < end; ++j) {
        int s = g_csrsrc[j];
        float4 v = __ldg(&p4[(size_t)s * 32 + lane]);
        acc.x += v.x; acc.y += v.y; acc.z += v.z; acc.w += v.w;
    }
    float di = g_dinv[warp];
    float4 bb = ((const float4*)bias)[lane];
    float4 o;
    o.x = fmaxf(fmaf(acc.x, di, bb.x), 0.f);
    o.y = fmaxf(fmaf(acc.y, di, bb.y), 0.f);
    o.z = fmaxf(fmaf(acc.z, di, bb.z), 0.f);
    o.w = fmaxf(fmaf(acc.w, di, bb.w), 0.f);
    ((float4*)out)[(size_t)warp * 32 + lane] = o;
}

__global__ void k_agg40(const float* __restrict__ bias, float* __restrict__ out, int n) {
    int warp = (blockIdx.x * blockDim.x + threadIdx.x) >> 5;
    if (warp >= n) return;
    int lane = threadIdx.x & 31;
    bool act = lane < 20;
    const float2* p2 = (const float2*)g_p;
    float2 acc = make_float2(0.f, 0.f);
    if (act) acc = p2[(size_t)warp * 20 + lane];          // self loop
    int j = g_rowptr[warp];
    int end = g_rowptr[warp + 1];
    for (; j + 4 <= end; j += 4) {
        int s0 = g_csrsrc[j], s1 = g_csrsrc[j + 1], s2 = g_csrsrc[j + 2], s3 = g_csrsrc[j + 3];
        if (act) {
            float2 v0 = __ldg(&p2[(size_t)s0 * 20 + lane]);
            float2 v1 = __ldg(&p2[(size_t)s1 * 20 + lane]);
            float2 v2 = __ldg(&p2[(size_t)s2 * 20 + lane]);
            float2 v3 = __ldg(&p2[(size_t)s3 * 20 + lane]);
            acc.x += v0.x + v1.x + v2.x + v3.x;
            acc.y += v0.y + v1.y + v2.y + v3.y;
        }
    }
    for (; j < end; ++j) {
        int s = g_csrsrc[j];
        if (act) {
            float2 v = __ldg(&p2[(size_t)s * 20 + lane]);
            acc.x += v.x; acc.y += v.y;
        }
    }
    if (act) {
        float di = g_dinv[warp];
        float2 bb = ((const float2*)bias)[lane];
        float2 o;
        o.x = fmaf(acc.x, di, bb.x);
        o.y = fmaf(acc.y, di, bb.y);
        ((float2*)out)[(size_t)warp * 20 + lane] = o;
    }
}

// ---------------- launch ----------------
extern "C" void kernel_launch(void* const* d_in, const int* in_sizes, int n_in,
                              void* d_out, int out_size) {
    const float* x  = (const float*)d_in[0];
    const void*  ei = d_in[1];
    const float* W1 = (const float*)d_in[2];
    const float* b1 = (const float*)d_in[3];
    const float* W2 = (const float*)d_in[4];
    const float* b2 = (const float*)d_in[5];

    int n = in_sizes[0] / 128;
    int E = in_sizes[1] / 2;

    float* out    = (float*)d_out;
    float* logits = out;                       // [n, 40]
    float* hidden;
    if ((size_t)out_size >= (size_t)n * (40 + 128)) {
        hidden = out + (size_t)n * 40;         // [n, 128]
    } else {
        cudaGetSymbolAddress((void**)&hidden, g_hidden_scratch);
    }

    void* deg_ptr = nullptr;
    cudaGetSymbolAddress(&deg_ptr, g_deg);

    int nb_n = (n + 255) / 256;
    int nb_e = (E + 255) / 256;
    int nb_scan = (n + 1023) / 1024;
    int nb_warp = (n + 7) / 8;

    // edge dtype detection + CSR build
    k_detect     <<<1, 1>>>((const int*)ei);
    cudaMemsetAsync(deg_ptr, 0, (size_t)n * sizeof(int));
    k_deg_count  <<<nb_e, 256>>>(ei, E, n);
    k_scan_block <<<nb_scan, 256>>>(n);
    k_scan_top   <<<1, 128>>>(nb_scan);
    k_scan_finish<<<nb_n, 256>>>(n, E);
    k_scatter    <<<nb_e, 256>>>(ei, E, n);

    // layer 1
    k_gemm<64><<<dim3(nb_n, 2), 256>>>(x, W1, 128, 128, n);
    k_agg128  <<<nb_warp, 256>>>(b1, hidden, n);

    // layer 2
    k_gemm<40><<<dim3(nb_n, 1), 256>>>(hidden, W2, 40, 40, n);
    k_agg40   <<<nb_warp, 256>>>(b2, logits, n);
}

// round 4
// speedup vs baseline: 1.0916x; 1.0915x over previous
#include <cuda_runtime.h>
#include <stdint.h>

// Fixed problem shape: N=100000 nodes, E=1600000 edges, dims 128 -> 128 -> 40.
#define NMAX 100352
#define EMAX 1600000

// ---------------- device scratch (no allocations allowed) ----------------
__device__ int   g_deg[NMAX];
__device__ int   g_rowptr[NMAX + 1];
__device__ int   g_cursor[NMAX];
__device__ int   g_blocksums[256];
__device__ int   g_csrsrc[EMAX];
__device__ float g_dinv[NMAX];
__device__ float g_p[(size_t)NMAX * 128];              // unscaled features h = X@W
__device__ float g_hidden_scratch[(size_t)NMAX * 128]; // fallback hidden storage
__device__ int   g_idx64;                              // 1 if edge_index is int64

// ---------------- packed f32x2 helpers ----------------
__device__ __forceinline__ unsigned long long pack2(float lo, float hi) {
    unsigned long long r;
    asm("mov.b64 %0, {%1, %2};" : "=l"(r) : "f"(lo), "f"(hi));
    return r;
}
__device__ __forceinline__ void unpack2(unsigned long long v, float& lo, float& hi) {
    asm("mov.b64 {%0, %1}, %2;" : "=f"(lo), "=f"(hi) : "l"(v));
}
__device__ __forceinline__ unsigned long long fma2(unsigned long long a,
                                                   unsigned long long b,
                                                   unsigned long long c) {
    unsigned long long d;
    asm("fma.rn.f32x2 %0, %1, %2, %3;" : "=l"(d) : "l"(a), "l"(b), "l"(c));
    return d;
}

// ---------------- dtype detection ----------------
__global__ void k_detect(const int* __restrict__ ei32) {
    int any = 0;
#pragma unroll
    for (int k = 0; k < 64; ++k) any |= ei32[2 * k + 1];
    g_idx64 = (any == 0) ? 1 : 0;
}

__device__ __forceinline__ int edge_at(const void* ei, long long i) {
    if (g_idx64) return (int)((const long long*)ei)[i];
    return ((const int*)ei)[i];
}

// ---------------- degree / CSR build ----------------
__global__ void k_deg_count(const void* __restrict__ ei, int E, int n) {
    int e = blockIdx.x * blockDim.x + threadIdx.x;
    if (e < E) {
        int d = edge_at(ei, (long long)E + e);
        if ((unsigned)d < (unsigned)n) atomicAdd(&g_deg[d], 1);
    }
}

__global__ void k_scan_block(int n) {
    __shared__ int ssum[256];
    int tid = threadIdx.x;
    int base = blockIdx.x * 1024 + tid * 4;
    int v0 = (base + 0 < n) ? g_deg[base + 0] : 0;
    int v1 = (base + 1 < n) ? g_deg[base + 1] : 0;
    int v2 = (base + 2 < n) ? g_deg[base + 2] : 0;
    int v3 = (base + 3 < n) ? g_deg[base + 3] : 0;
    int p0 = 0, p1 = v0, p2 = v0 + v1, p3 = v0 + v1 + v2;
    int total = p3 + v3;
    ssum[tid] = total;
    __syncthreads();
    for (int off = 1; off < 256; off <<= 1) {
        int v = 0;
        if (tid >= off) v = ssum[tid - off];
        __syncthreads();
        if (tid >= off) ssum[tid] += v;
        __syncthreads();
    }
    int excl = ssum[tid] - total;
    if (base + 0 < n) g_rowptr[base + 0] = excl + p0;
    if (base + 1 < n) g_rowptr[base + 1] = excl + p1;
    if (base + 2 < n) g_rowptr[base + 2] = excl + p2;
    if (base + 3 < n) g_rowptr[base + 3] = excl + p3;
    if (tid == 255) g_blocksums[blockIdx.x] = ssum[255];
}

__global__ void k_scan_top(int nb) {
    __shared__ int s[128];
    int tid = threadIdx.x;
    int orig = (tid < nb) ? g_blocksums[tid] : 0;
    s[tid] = orig;
    __syncthreads();
    for (int off = 1; off < 128; off <<= 1) {
        int v = 0;
        if (tid >= off) v = s[tid - off];
        __syncthreads();
        if (tid >= off) s[tid] += v;
        __syncthreads();
    }
    if (tid < nb) g_blocksums[tid] = s[tid] - orig;
}

__global__ void k_scan_finish(int n, int E) {
    int i = blockIdx.x * blockDim.x + threadIdx.x;
    if (i < n) {
        int v = g_rowptr[i] + g_blocksums[i >> 10];
        g_rowptr[i] = v;
        g_cursor[i] = v;
        g_dinv[i]   = rsqrtf((float)(g_deg[i] + 1));
    }
    if (i == 0) g_rowptr[n] = E;
}

__global__ void k_scatter(const void* __restrict__ ei, int E, int n) {
    int e = blockIdx.x * blockDim.x + threadIdx.x;
    if (e < E) {
        int s = edge_at(ei, e);
        int d = edge_at(ei, (long long)E + e);
        if ((unsigned)d < (unsigned)n && (unsigned)s < (unsigned)n) {
            int pos = atomicAdd(&g_cursor[d], 1);
            if (pos < EMAX) g_csrsrc[pos] = s;
        }
    }
}

// ---------------- GEMM (unscaled): P[node, f0:f0+FT] = X[node,:] @ W[:, f0:f0+FT] ----
template <int FT>
__launch_bounds__(256)
__global__ void k_gemm(const float* __restrict__ X, const float* __restrict__ W,
                       int ldw, int ldp, int n) {
    __shared__ __align__(16) float sW[32 * FT];
    __shared__ __align__(16) float sx[256 * 33];
    const int tid = threadIdx.x;
    const int n0 = blockIdx.x * 256;
    const int f0 = blockIdx.y * FT;
    unsigned long long acc2[FT / 2];
#pragma unroll
    for (int j = 0; j < FT / 2; ++j) acc2[j] = 0ULL;

    for (int kc = 0; kc < 4; ++kc) {
        __syncthreads();
        for (int t = tid; t < 256 * 8; t += 256) {
            int r = t >> 3, c4 = (t & 7) * 4;
            int node = n0 + r;
            float4 xv = make_float4(0.f, 0.f, 0.f, 0.f);
            if (node < n)
                xv = *(const float4*)(X + (size_t)node * 128 + kc * 32 + c4);
            float* d = &sx[r * 33 + c4];
            d[0] = xv.x; d[1] = xv.y; d[2] = xv.z; d[3] = xv.w;
        }
        for (int t = tid; t < 32 * (FT / 4); t += 256) {
            int k = t / (FT / 4), q = t % (FT / 4);
            float4 wv = *(const float4*)(W + (size_t)(kc * 32 + k) * ldw + f0 + q * 4);
            *(float4*)(&sW[k * FT + q * 4]) = wv;
        }
        __syncthreads();
#pragma unroll
        for (int kk = 0; kk < 32; ++kk) {
            float xv = sx[tid * 33 + kk];
            unsigned long long xx = pack2(xv, xv);
            const ulonglong2* wrow = (const ulonglong2*)(&sW[kk * FT]);
#pragma unroll
            for (int j4 = 0; j4 < FT / 4; ++j4) {
                ulonglong2 w = wrow[j4];
                acc2[j4 * 2 + 0] = fma2(xx, w.x, acc2[j4 * 2 + 0]);
                acc2[j4 * 2 + 1] = fma2(xx, w.y, acc2[j4 * 2 + 1]);
            }
        }
    }
    int node = n0 + tid;
    if (node < n) {
        float* P = g_p + (size_t)node * ldp + f0;
#pragma unroll
        for (int j4 = 0; j4 < FT / 4; ++j4) {
            float4 o;
            unpack2(acc2[j4 * 2 + 0], o.x, o.y);
            unpack2(acc2[j4 * 2 + 1], o.z, o.w);
            *(float4*)(P + j4 * 4) = o;
        }
    }
}

// ---------------- aggregation: one warp per node, dinv folded at gather ----
__global__ void k_agg128(const float* __restrict__ bias, float* __restrict__ out, int n) {
    int warp = (blockIdx.x * blockDim.x + threadIdx.x) >> 5;
    if (warp >= n) return;
    int lane = threadIdx.x & 31;
    const float4* p4 = (const float4*)g_p;
    float diw = g_dinv[warp];
    float4 self = p4[(size_t)warp * 32 + lane];
    float4 acc;
    acc.x = self.x * diw; acc.y = self.y * diw;
    acc.z = self.z * diw; acc.w = self.w * diw;
    int j = g_rowptr[warp];
    int end = g_rowptr[warp + 1];
    for (; j + 4 <= end; j += 4) {
        int s0 = g_csrsrc[j], s1 = g_csrsrc[j + 1], s2 = g_csrsrc[j + 2], s3 = g_csrsrc[j + 3];
        float d0 = g_dinv[s0], d1 = g_dinv[s1], d2 = g_dinv[s2], d3 = g_dinv[s3];
        float4 v0 = __ldg(&p4[(size_t)s0 * 32 + lane]);
        float4 v1 = __ldg(&p4[(size_t)s1 * 32 + lane]);
        float4 v2 = __ldg(&p4[(size_t)s2 * 32 + lane]);
        float4 v3 = __ldg(&p4[(size_t)s3 * 32 + lane]);
        acc.x = fmaf(v0.x, d0, fmaf(v1.x, d1, fmaf(v2.x, d2, fmaf(v3.x, d3, acc.x))));
        acc.y = fmaf(v0.y, d0, fmaf(v1.y, d1, fmaf(v2.y, d2, fmaf(v3.y, d3, acc.y))));
        acc.z = fmaf(v0.z, d0, fmaf(v1.z, d1, fmaf(v2.z, d2, fmaf(v3.z, d3, acc.z))));
        acc.w = fmaf(v0.w, d0, fmaf(v1.w, d1, fmaf(v2.w, d2, fmaf(v3.w, d3, acc.w))));
    }
    for (; j < end; ++j) {
        int s = g_csrsrc[j];
        float d = g_dinv[s];
        float4 v = __ldg(&p4[(size_t)s * 32 + lane]);
        acc.x = fmaf(v.x, d, acc.x); acc.y = fmaf(v.y, d, acc.y);
        acc.z = fmaf(v.z, d, acc.z); acc.w = fmaf(v.w, d, acc.w);
    }
    float4 bb = ((const float4*)bias)[lane];
    float4 o;
    o.x = fmaxf(fmaf(acc.x, diw, bb.x), 0.f);
    o.y = fmaxf(fmaf(acc.y, diw, bb.y), 0.f);
    o.z = fmaxf(fmaf(acc.z, diw, bb.z), 0.f);
    o.w = fmaxf(fmaf(acc.w, diw, bb.w), 0.f);
    ((float4*)out)[(size_t)warp * 32 + lane] = o;
}

__global__ void k_agg40(const float* __restrict__ bias, float* __restrict__ out, int n) {
    int warp = (blockIdx.x * blockDim.x + threadIdx.x) >> 5;
    if (warp >= n) return;
    int lane = threadIdx.x & 31;
    bool act = lane < 20;
    const float2* p2 = (const float2*)g_p;
    float diw = g_dinv[warp];
    float2 acc = make_float2(0.f, 0.f);
    if (act) {
        float2 self = p2[(size_t)warp * 20 + lane];
        acc.x = self.x * diw; acc.y = self.y * diw;
    }
    int j = g_rowptr[warp];
    int end = g_rowptr[warp + 1];
    for (; j + 4 <= end; j += 4) {
        int s0 = g_csrsrc[j], s1 = g_csrsrc[j + 1], s2 = g_csrsrc[j + 2], s3 = g_csrsrc[j + 3];
        float d0 = g_dinv[s0], d1 = g_dinv[s1], d2 = g_dinv[s2], d3 = g_dinv[s3];
        if (act) {
            float2 v0 = __ldg(&p2[(size_t)s0 * 20 + lane]);
            float2 v1 = __ldg(&p2[(size_t)s1 * 20 + lane]);
            float2 v2 = __ldg(&p2[(size_t)s2 * 20 + lane]);
            float2 v3 = __ldg(&p2[(size_t)s3 * 20 + lane]);
            acc.x = fmaf(v0.x, d0, fmaf(v1.x, d1, fmaf(v2.x, d2, fmaf(v3.x, d3, acc.x))));
            acc.y = fmaf(v0.y, d0, fmaf(v1.y, d1, fmaf(v2.y, d2, fmaf(v3.y, d3, acc.y))));
        }
    }
    for (; j < end; ++j) {
        int s = g_csrsrc[j];
        float d = g_dinv[s];
        if (act) {
            float2 v = __ldg(&p2[(size_t)s * 20 + lane]);
            acc.x = fmaf(v.x, d, acc.x); acc.y = fmaf(v.y, d, acc.y);
        }
    }
    if (act) {
        float2 bb = ((const float2*)bias)[lane];
        float2 o;
        o.x = fmaf(acc.x, diw, bb.x);
        o.y = fmaf(acc.y, diw, bb.y);
        ((float2*)out)[(size_t)warp * 20 + lane] = o;
    }
}

// ---------------- launch ----------------
extern "C" void kernel_launch(void* const* d_in, const int* in_sizes, int n_in,
                              void* d_out, int out_size) {
    const float* x  = (const float*)d_in[0];
    const void*  ei = d_in[1];
    const float* W1 = (const float*)d_in[2];
    const float* b1 = (const float*)d_in[3];
    const float* W2 = (const float*)d_in[4];
    const float* b2 = (const float*)d_in[5];

    int n = in_sizes[0] / 128;
    int E = in_sizes[1] / 2;

    float* out    = (float*)d_out;
    float* logits = out;                       // [n, 40]
    float* hidden;
    if ((size_t)out_size >= (size_t)n * (40 + 128)) {
        hidden = out + (size_t)n * 40;         // [n, 128]
    } else {
        cudaGetSymbolAddress((void**)&hidden, g_hidden_scratch);
    }

    void* deg_ptr = nullptr;
    cudaGetSymbolAddress(&deg_ptr, g_deg);

    int nb_n = (n + 255) / 256;
    int nb_e = (E + 255) / 256;
    int nb_scan = (n + 1023) / 1024;
    int nb_warp = (n + 7) / 8;

    // Fork a side stream for GEMM1 (independent of the CSR chain).
    cudaStream_t s2;
    cudaEvent_t evFork, evGemm;
    cudaStreamCreateWithFlags(&s2, cudaStreamNonBlocking);
    cudaEventCreateWithFlags(&evFork, cudaEventDisableTiming);
    cudaEventCreateWithFlags(&evGemm, cudaEventDisableTiming);

    cudaEventRecord(evFork, 0);
    cudaStreamWaitEvent(s2, evFork, 0);
    // Chain B (side stream): unscaled GEMM1 — needs only x, W1.
    k_gemm<64><<<dim3(nb_n, 2), 256, 0, s2>>>(x, W1, 128, 128, n);
    cudaEventRecord(evGemm, s2);

    // Chain A (main stream): edge dtype detection + CSR build.
    k_detect     <<<1, 1>>>((const int*)ei);
    cudaMemsetAsync(deg_ptr, 0, (size_t)n * sizeof(int));
    k_deg_count  <<<nb_e, 256>>>(ei, E, n);
    k_scan_block <<<nb_scan, 256>>>(n);
    k_scan_top   <<<1, 128>>>(nb_scan);
    k_scan_finish<<<nb_n, 256>>>(n, E);
    k_scatter    <<<nb_e, 256>>>(ei, E, n);

    // Join, then the serial tail.
    cudaStreamWaitEvent(0, evGemm, 0);
    k_agg128  <<<nb_warp, 256>>>(b1, hidden, n);
    k_gemm<40><<<dim3(nb_n, 1), 256>>>(hidden, W2, 40, 40, n);
    k_agg40   <<<nb_warp, 256>>>(b2, logits, n);

    cudaEventDestroy(evFork);
    cudaEventDestroy(evGemm);
    cudaStreamDestroy(s2);
}

// round 5
// speedup vs baseline: 1.0938x; 1.0020x over previous
#include <cuda_runtime.h>
#include <cuda_fp16.h>
#include <stdint.h>

// Fixed problem shape: N=100000 nodes, E=1600000 edges, dims 128 -> 128 -> 40.
#define NMAX 100352
#define EMAX 1600000

// ---------------- device scratch (no allocations allowed) ----------------
__device__ int    g_deg[NMAX];
__device__ int    g_rowptr[NMAX + 1];
__device__ int    g_cursor[NMAX];
__device__ int    g_blocksums[256];
__device__ int    g_csrsrc[EMAX];
__device__ float  g_dinv[NMAX];
__device__ __half g_ph[(size_t)NMAX * 128];             // fp16 messages h = X@W
__device__ float  g_hidden_scratch[(size_t)NMAX * 128]; // fallback hidden storage
__device__ int    g_idx64;                              // 1 if edge_index is int64

// ---------------- packed f32x2 helpers ----------------
__device__ __forceinline__ unsigned long long pack2(float lo, float hi) {
    unsigned long long r;
    asm("mov.b64 %0, {%1, %2};" : "=l"(r) : "f"(lo), "f"(hi));
    return r;
}
__device__ __forceinline__ void unpack2(unsigned long long v, float& lo, float& hi) {
    asm("mov.b64 {%0, %1}, %2;" : "=f"(lo), "=f"(hi) : "l"(v));
}
__device__ __forceinline__ unsigned long long fma2(unsigned long long a,
                                                   unsigned long long b,
                                                   unsigned long long c) {
    unsigned long long d;
    asm("fma.rn.f32x2 %0, %1, %2, %3;" : "=l"(d) : "l"(a), "l"(b), "l"(c));
    return d;
}

// ---------------- dtype detection ----------------
__global__ void k_detect(const int* __restrict__ ei32) {
    int any = 0;
#pragma unroll
    for (int k = 0; k < 64; ++k) any |= ei32[2 * k + 1];
    g_idx64 = (any == 0) ? 1 : 0;
}

__device__ __forceinline__ int edge_at(const void* ei, long long i) {
    if (g_idx64) return (int)((const long long*)ei)[i];
    return ((const int*)ei)[i];
}

// ---------------- degree / CSR build ----------------
__global__ void k_deg_count(const void* __restrict__ ei, int E, int n) {
    int e = blockIdx.x * blockDim.x + threadIdx.x;
    if (e < E) {
        int d = edge_at(ei, (long long)E + e);
        if ((unsigned)d < (unsigned)n) atomicAdd(&g_deg[d], 1);
    }
}

__global__ void k_scan_block(int n) {
    __shared__ int ssum[256];
    int tid = threadIdx.x;
    int base = blockIdx.x * 1024 + tid * 4;
    int v0 = (base + 0 < n) ? g_deg[base + 0] : 0;
    int v1 = (base + 1 < n) ? g_deg[base + 1] : 0;
    int v2 = (base + 2 < n) ? g_deg[base + 2] : 0;
    int v3 = (base + 3 < n) ? g_deg[base + 3] : 0;
    int p0 = 0, p1 = v0, p2 = v0 + v1, p3 = v0 + v1 + v2;
    int total = p3 + v3;
    ssum[tid] = total;
    __syncthreads();
    for (int off = 1; off < 256; off <<= 1) {
        int v = 0;
        if (tid >= off) v = ssum[tid - off];
        __syncthreads();
        if (tid >= off) ssum[tid] += v;
        __syncthreads();
    }
    int excl = ssum[tid] - total;
    if (base + 0 < n) g_rowptr[base + 0] = excl + p0;
    if (base + 1 < n) g_rowptr[base + 1] = excl + p1;
    if (base + 2 < n) g_rowptr[base + 2] = excl + p2;
    if (base + 3 < n) g_rowptr[base + 3] = excl + p3;
    if (tid == 255) g_blocksums[blockIdx.x] = ssum[255];
}

__global__ void k_scan_top(int nb) {
    __shared__ int s[128];
    int tid = threadIdx.x;
    int orig = (tid < nb) ? g_blocksums[tid] : 0;
    s[tid] = orig;
    __syncthreads();
    for (int off = 1; off < 128; off <<= 1) {
        int v = 0;
        if (tid >= off) v = s[tid - off];
        __syncthreads();
        if (tid >= off) s[tid] += v;
        __syncthreads();
    }
    if (tid < nb) g_blocksums[tid] = s[tid] - orig;
}

__global__ void k_scan_finish(int n, int E) {
    int i = blockIdx.x * blockDim.x + threadIdx.x;
    if (i < n) {
        int v = g_rowptr[i] + g_blocksums[i >> 10];
        g_rowptr[i] = v;
        g_cursor[i] = v;
        g_dinv[i]   = rsqrtf((float)(g_deg[i] + 1));
    }
    if (i == 0) g_rowptr[n] = E;
}

__global__ void k_scatter(const void* __restrict__ ei, int E, int n) {
    int e = blockIdx.x * blockDim.x + threadIdx.x;
    if (e < E) {
        int s = edge_at(ei, e);
        int d = edge_at(ei, (long long)E + e);
        if ((unsigned)d < (unsigned)n && (unsigned)s < (unsigned)n) {
            int pos = atomicAdd(&g_cursor[d], 1);
            if (pos < EMAX) g_csrsrc[pos] = s;
        }
    }
}

// ---------------- GEMM: g_ph[node, f0:f0+FT] = fp16(X[node,:] @ W[:, f0:f0+FT]) ----
template <int FT>
__launch_bounds__(256)
__global__ void k_gemm(const float* __restrict__ X, const float* __restrict__ W,
                       int ldw, int ldp, int n) {
    __shared__ __align__(16) float sW[32 * FT];
    __shared__ __align__(16) float sx[256 * 33];
    const int tid = threadIdx.x;
    const int n0 = blockIdx.x * 256;
    const int f0 = blockIdx.y * FT;
    unsigned long long acc2[FT / 2];
#pragma unroll
    for (int j = 0; j < FT / 2; ++j) acc2[j] = 0ULL;

    for (int kc = 0; kc < 4; ++kc) {
        __syncthreads();
        for (int t = tid; t < 256 * 8; t += 256) {
            int r = t >> 3, c4 = (t & 7) * 4;
            int node = n0 + r;
            float4 xv = make_float4(0.f, 0.f, 0.f, 0.f);
            if (node < n)
                xv = *(const float4*)(X + (size_t)node * 128 + kc * 32 + c4);
            float* d = &sx[r * 33 + c4];
            d[0] = xv.x; d[1] = xv.y; d[2] = xv.z; d[3] = xv.w;
        }
        for (int t = tid; t < 32 * (FT / 4); t += 256) {
            int k = t / (FT / 4), q = t % (FT / 4);
            float4 wv = *(const float4*)(W + (size_t)(kc * 32 + k) * ldw + f0 + q * 4);
            *(float4*)(&sW[k * FT + q * 4]) = wv;
        }
        __syncthreads();
#pragma unroll
        for (int kk = 0; kk < 32; ++kk) {
            float xv = sx[tid * 33 + kk];
            unsigned long long xx = pack2(xv, xv);
            const ulonglong2* wrow = (const ulonglong2*)(&sW[kk * FT]);
#pragma unroll
            for (int j4 = 0; j4 < FT / 4; ++j4) {
                ulonglong2 w = wrow[j4];
                acc2[j4 * 2 + 0] = fma2(xx, w.x, acc2[j4 * 2 + 0]);
                acc2[j4 * 2 + 1] = fma2(xx, w.y, acc2[j4 * 2 + 1]);
            }
        }
    }
    int node = n0 + tid;
    if (node < n) {
        __half2* P = (__half2*)(g_ph + (size_t)node * ldp + f0);
#pragma unroll
        for (int j2 = 0; j2 < FT / 2; ++j2) {
            float2 f;
            unpack2(acc2[j2], f.x, f.y);
            P[j2] = __float22half2_rn(f);
        }
    }
}

// ---------------- aggregation: one warp per node, fp16 messages, fp32 accum ----
__device__ __forceinline__ float4 cvt4(uint2 r) {
    float2 a = __half22float2(*(const __half2*)&r.x);
    float2 b = __half22float2(*(const __half2*)&r.y);
    return make_float4(a.x, a.y, b.x, b.y);
}

__global__ void k_agg128(const float* __restrict__ bias, float* __restrict__ out, int n) {
    int warp = (blockIdx.x * blockDim.x + threadIdx.x) >> 5;
    if (warp >= n) return;
    int lane = threadIdx.x & 31;
    const uint2* p = (const uint2*)g_ph;   // 4 halves per uint2; node stride = 32
    float diw = g_dinv[warp];
    float4 self = cvt4(p[(size_t)warp * 32 + lane]);
    float4 acc;
    acc.x = self.x * diw; acc.y = self.y * diw;
    acc.z = self.z * diw; acc.w = self.w * diw;
    int j = g_rowptr[warp];
    int end = g_rowptr[warp + 1];
    for (; j + 4 <= end; j += 4) {
        int s0 = g_csrsrc[j], s1 = g_csrsrc[j + 1], s2 = g_csrsrc[j + 2], s3 = g_csrsrc[j + 3];
        float d0 = g_dinv[s0], d1 = g_dinv[s1], d2 = g_dinv[s2], d3 = g_dinv[s3];
        float4 v0 = cvt4(__ldg(&p[(size_t)s0 * 32 + lane]));
        float4 v1 = cvt4(__ldg(&p[(size_t)s1 * 32 + lane]));
        float4 v2 = cvt4(__ldg(&p[(size_t)s2 * 32 + lane]));
        float4 v3 = cvt4(__ldg(&p[(size_t)s3 * 32 + lane]));
        acc.x = fmaf(v0.x, d0, fmaf(v1.x, d1, fmaf(v2.x, d2, fmaf(v3.x, d3, acc.x))));
        acc.y = fmaf(v0.y, d0, fmaf(v1.y, d1, fmaf(v2.y, d2, fmaf(v3.y, d3, acc.y))));
        acc.z = fmaf(v0.z, d0, fmaf(v1.z, d1, fmaf(v2.z, d2, fmaf(v3.z, d3, acc.z))));
        acc.w = fmaf(v0.w, d0, fmaf(v1.w, d1, fmaf(v2.w, d2, fmaf(v3.w, d3, acc.w))));
    }
    for (; j < end; ++j) {
        int s = g_csrsrc[j];
        float d = g_dinv[s];
        float4 v = cvt4(__ldg(&p[(size_t)s * 32 + lane]));
        acc.x = fmaf(v.x, d, acc.x); acc.y = fmaf(v.y, d, acc.y);
        acc.z = fmaf(v.z, d, acc.z); acc.w = fmaf(v.w, d, acc.w);
    }
    float4 bb = ((const float4*)bias)[lane];
    float4 o;
    o.x = fmaxf(fmaf(acc.x, diw, bb.x), 0.f);
    o.y = fmaxf(fmaf(acc.y, diw, bb.y), 0.f);
    o.z = fmaxf(fmaf(acc.z, diw, bb.z), 0.f);
    o.w = fmaxf(fmaf(acc.w, diw, bb.w), 0.f);
    ((float4*)out)[(size_t)warp * 32 + lane] = o;
}

__global__ void k_agg40(const float* __restrict__ bias, float* __restrict__ out, int n) {
    int warp = (blockIdx.x * blockDim.x + threadIdx.x) >> 5;
    if (warp >= n) return;
    int lane = threadIdx.x & 31;
    bool act = lane < 20;
    const unsigned int* p = (const unsigned int*)g_ph; // 2 halves per uint; node stride = 20
    float diw = g_dinv[warp];
    float2 acc = make_float2(0.f, 0.f);
    if (act) {
        float2 self = __half22float2(*(const __half2*)&p[(size_t)warp * 20 + lane]);
        acc.x = self.x * diw; acc.y = self.y * diw;
    }
    int j = g_rowptr[warp];
    int end = g_rowptr[warp + 1];
    for (; j + 4 <= end; j += 4) {
        int s0 = g_csrsrc[j], s1 = g_csrsrc[j + 1], s2 = g_csrsrc[j + 2], s3 = g_csrsrc[j + 3];
        float d0 = g_dinv[s0], d1 = g_dinv[s1], d2 = g_dinv[s2], d3 = g_dinv[s3];
        if (act) {
            unsigned int r0 = __ldg(&p[(size_t)s0 * 20 + lane]);
            unsigned int r1 = __ldg(&p[(size_t)s1 * 20 + lane]);
            unsigned int r2 = __ldg(&p[(size_t)s2 * 20 + lane]);
            unsigned int r3 = __ldg(&p[(size_t)s3 * 20 + lane]);
            float2 v0 = __half22float2(*(const __half2*)&r0);
            float2 v1 = __half22float2(*(const __half2*)&r1);
            float2 v2 = __half22float2(*(const __half2*)&r2);
            float2 v3 = __half22float2(*(const __half2*)&r3);
            acc.x = fmaf(v0.x, d0, fmaf(v1.x, d1, fmaf(v2.x, d2, fmaf(v3.x, d3, acc.x))));
            acc.y = fmaf(v0.y, d0, fmaf(v1.y, d1, fmaf(v2.y, d2, fmaf(v3.y, d3, acc.y))));
        }
    }
    for (; j < end; ++j) {
        int s = g_csrsrc[j];
        float d = g_dinv[s];
        if (act) {
            unsigned int r = __ldg(&p[(size_t)s * 20 + lane]);
            float2 v = __half22float2(*(const __half2*)&r);
            acc.x = fmaf(v.x, d, acc.x); acc.y = fmaf(v.y, d, acc.y);
        }
    }
    if (act) {
        float2 bb = ((const float2*)bias)[lane];
        float2 o;
        o.x = fmaf(acc.x, diw, bb.x);
        o.y = fmaf(acc.y, diw, bb.y);
        ((float2*)out)[(size_t)warp * 20 + lane] = o;
    }
}

// ---------------- launch ----------------
extern "C" void kernel_launch(void* const* d_in, const int* in_sizes, int n_in,
                              void* d_out, int out_size) {
    const float* x  = (const float*)d_in[0];
    const void*  ei = d_in[1];
    const float* W1 = (const float*)d_in[2];
    const float* b1 = (const float*)d_in[3];
    const float* W2 = (const float*)d_in[4];
    const float* b2 = (const float*)d_in[5];

    int n = in_sizes[0] / 128;
    int E = in_sizes[1] / 2;

    float* out    = (float*)d_out;
    float* logits = out;                       // [n, 40]
    float* hidden;
    if ((size_t)out_size >= (size_t)n * (40 + 128)) {
        hidden = out + (size_t)n * 40;         // [n, 128]
    } else {
        cudaGetSymbolAddress((void**)&hidden, g_hidden_scratch);
    }

    void* deg_ptr = nullptr;
    cudaGetSymbolAddress(&deg_ptr, g_deg);

    int nb_n = (n + 255) / 256;
    int nb_e = (E + 255) / 256;
    int nb_scan = (n + 1023) / 1024;
    int nb_warp = (n + 7) / 8;

    // Fork a side stream for GEMM1 (independent of the CSR chain).
    cudaStream_t s2;
    cudaEvent_t evFork, evGemm;
    cudaStreamCreateWithFlags(&s2, cudaStreamNonBlocking);
    cudaEventCreateWithFlags(&evFork, cudaEventDisableTiming);
    cudaEventCreateWithFlags(&evGemm, cudaEventDisableTiming);

    cudaEventRecord(evFork, 0);
    cudaStreamWaitEvent(s2, evFork, 0);
    // Chain B (side stream): unscaled GEMM1 -> fp16 messages.
    k_gemm<64><<<dim3(nb_n, 2), 256, 0, s2>>>(x, W1, 128, 128, n);
    cudaEventRecord(evGemm, s2);

    // Chain A (main stream): edge dtype detection + CSR build.
    k_detect     <<<1, 1>>>((const int*)ei);
    cudaMemsetAsync(deg_ptr, 0, (size_t)n * sizeof(int));
    k_deg_count  <<<nb_e, 256>>>(ei, E, n);
    k_scan_block <<<nb_scan, 256>>>(n);
    k_scan_top   <<<1, 128>>>(nb_scan);
    k_scan_finish<<<nb_n, 256>>>(n, E);
    k_scatter    <<<nb_e, 256>>>(ei, E, n);

    // Join, then the serial tail.
    cudaStreamWaitEvent(0, evGemm, 0);
    k_agg128  <<<nb_warp, 256>>>(b1, hidden, n);
    k_gemm<40><<<dim3(nb_n, 1), 256>>>(hidden, W2, 40, 40, n);
    k_agg40   <<<nb_warp, 256>>>(b2, logits, n);

    cudaEventDestroy(evFork);
    cudaEventDestroy(evGemm);
    cudaStreamDestroy(s2);
}